// round 17
// baseline (speedup 1.0000x reference)
#include <cuda_runtime.h>
#include <cuda_bf16.h>

// ScalableHashGrid: InstantNGP-style multires hash grid encoding.
// 2^20 points x 10 levels x 4 feature dims, trilinear interp of 8 corners.
// Levels 0-2 dense (res 16/32/64), levels 3-9 hashed into 2^21-entry tables.
//
// R16 design (R6 structure + MLP-8 load scheduling; identical to R15 —
// resubmitted after an infra flake):
//  * 4 passes: {0,1,2,3} then hashed pairs {4,5},{6,7},{8,9}; hot table set
//    per pass <= 64MB (L2-resident within a pass).
//  * MLP-8: both levels' gather indices are computed first, then all 8
//    corner loads are issued back-to-back before any consumption. R13 SASS
//    (regs=32) showed ptxas was NOT hoisting the second level's loads, so
//    each thread had only 4 gathers in flight; the binder is L2 sector
//    bandwidth at 76% with issue=23% (long-scoreboard limited).
//  * evict_last cache hints removed: R13 measured them as a precise no-op.
//  * 2 threads per point (lane parity = x-corner side); x hash prime is 1 so
//    the cell's two x-corners share a 32B sector when ix is even -> adjacent
//    lanes merge in L1tex/L2.
//  * Streaming x reads (__ldcs) / out stores (__stcs) stay evict-first.
//  * Each thread-pair emits both levels of its pair: the two float4 stores
//    fill one aligned 32B sector (no partial-sector write amplification).

namespace {
constexpr int N_POINTS   = 1 << 20;
constexpr int NUM_LEVELS = 10;
constexpr unsigned HASH_MASK = (1u << 21) - 1u;
constexpr unsigned PRIME_Y = 2654435761u;
constexpr unsigned PRIME_Z = 805459861u;

// Per-level resolution and float4 offset into the concatenated table.
// SIZES = ceil8(min((r+1)^3, 2^21)): 4920, 35944, 274632, then 7 x 2097152.
constexpr int RES[NUM_LEVELS] = {16, 32, 64, 128, 256, 512, 1024, 2048, 4096, 8192};
constexpr int OFF[NUM_LEVELS] = {0, 4920, 40864, 315496, 2412648,
                                 4509800, 6606952, 8704104, 10801256, 12898408};

constexpr int THREADS = 256;
constexpr int BLOCKS  = (N_POINTS * 2) / THREADS;   // 8192 per pass
}

// Compute this lane's 4 corner indices and weights at level L (no loads).
template <int L>
__device__ __forceinline__ void level_prep(
    float x0, float x1, float x2, unsigned s,
    unsigned idx[4], float w[4])
{
    constexpr int      res   = RES[L];           // constant-expression eval
    constexpr unsigned off   = (unsigned)OFF[L]; // (no device odr-use of arrays)
    constexpr float    scale = (float)res - 1.0f;

    const float posx = x0 * scale + 0.5f;
    const float posy = x1 * scale + 0.5f;
    const float posz = x2 * scale + 0.5f;

    const float flx = floorf(posx);
    const float fly = floorf(posy);
    const float flz = floorf(posz);
    const float fx = posx - flx;
    const float fy = posy - fly;
    const float fz = posz - flz;

    const unsigned ix = (unsigned)flx;
    const unsigned iy = (unsigned)fly;
    const unsigned iz = (unsigned)flz;

    const unsigned xc = ix + s;                  // this lane's x corner
    const float    wx = s ? fx : (1.0f - fx);    // this lane's x weight

    if constexpr (L < 3) {
        // Dense: idx = x + y*(res+1) + z*(res+1)^2
        constexpr unsigned r1 = (unsigned)(res + 1);
        const unsigned y0 = iy * r1,      y1 = y0 + r1;
        const unsigned z0 = iz * r1 * r1, z1 = z0 + r1 * r1;
        idx[0] = off + (xc + y0 + z0);
        idx[1] = off + (xc + y1 + z0);
        idx[2] = off + (xc + y0 + z1);
        idx[3] = off + (xc + y1 + z1);
    } else {
        // Hashed: (x*1 ^ y*P1 ^ z*P2) & (2^21-1)
        const unsigned hy0 = iy * PRIME_Y, hy1 = hy0 + PRIME_Y;
        const unsigned hz0 = iz * PRIME_Z, hz1 = hz0 + PRIME_Z;
        idx[0] = off + ((xc ^ hy0 ^ hz0) & HASH_MASK);
        idx[1] = off + ((xc ^ hy1 ^ hz0) & HASH_MASK);
        idx[2] = off + ((xc ^ hy0 ^ hz1) & HASH_MASK);
        idx[3] = off + ((xc ^ hy1 ^ hz1) & HASH_MASK);
    }

    // (y,z) = (0,0),(1,0),(0,1),(1,1)
    w[0] = wx * (1.0f - fy) * (1.0f - fz);
    w[1] = wx * fy          * (1.0f - fz);
    w[2] = wx * (1.0f - fy) * fz;
    w[3] = wx * fy          * fz;
}

// Weighted sum of 4 corner embeddings.
__device__ __forceinline__ float4 wsum4(const float4 e[4], const float w[4])
{
    float4 acc;
    acc.x = w[0]*e[0].x + w[1]*e[1].x + w[2]*e[2].x + w[3]*e[3].x;
    acc.y = w[0]*e[0].y + w[1]*e[1].y + w[2]*e[2].y + w[3]*e[3].y;
    acc.z = w[0]*e[0].z + w[1]*e[1].z + w[2]*e[2].z + w[3]*e[3].z;
    acc.w = w[0]*e[0].w + w[1]*e[1].w + w[2]*e[2].w + w[3]*e[3].w;
    return acc;
}

// Levels L0, L0+1 for one point: 8 gathers issued before any consumption.
template <int L0>
__device__ __forceinline__ void do_pair(
    const float4* __restrict__ table, float4* __restrict__ out,
    float x0, float x1, float x2, unsigned s, int n)
{
    unsigned ia[4], ib[4];
    float    wa[4], wb[4];
    level_prep<L0>    (x0, x1, x2, s, ia, wa);
    level_prep<L0 + 1>(x0, x1, x2, s, ib, wb);

    // Issue all 8 independent gathers back-to-back (MLP = 8 per thread).
    float4 ea[4], eb[4];
#pragma unroll
    for (int i = 0; i < 4; i++) ea[i] = __ldg(table + ia[i]);
#pragma unroll
    for (int i = 0; i < 4; i++) eb[i] = __ldg(table + ib[i]);

    float4 a0 = wsum4(ea, wa);
    float4 a1 = wsum4(eb, wb);

    // Sum the two x-sides across the lane pair.
    a0.x += __shfl_xor_sync(0xffffffffu, a0.x, 1);
    a0.y += __shfl_xor_sync(0xffffffffu, a0.y, 1);
    a0.z += __shfl_xor_sync(0xffffffffu, a0.z, 1);
    a0.w += __shfl_xor_sync(0xffffffffu, a0.w, 1);
    a1.x += __shfl_xor_sync(0xffffffffu, a1.x, 1);
    a1.y += __shfl_xor_sync(0xffffffffu, a1.y, 1);
    a1.z += __shfl_xor_sync(0xffffffffu, a1.z, 1);
    a1.w += __shfl_xor_sync(0xffffffffu, a1.w, 1);

    if (s == 0) {
        float4* o = out + (n * NUM_LEVELS + L0);
        __stcs(o + 0, a0);   // streaming store: evict-first
        __stcs(o + 1, a1);
    }
}

__device__ __forceinline__ void load_point(
    const float* __restrict__ x, int n, float& x0, float& x1, float& x2)
{
    // Streaming reads (evict-first): x is touched once per pass.
    x0 = (__ldcs(&x[3 * n + 0]) + 1.0f) * 0.5f;
    x1 = (__ldcs(&x[3 * n + 1]) + 1.0f) * 0.5f;
    x2 = (__ldcs(&x[3 * n + 2]) + 1.0f) * 0.5f;
}

// Pass A: levels 0..3 (dense 0-2 + hashed 3), two 8-deep pair groups.
__global__ __launch_bounds__(THREADS)
void hashgrid_quad_kernel(const float* __restrict__ x,
                          const float4* __restrict__ table,
                          float4* __restrict__ out)
{
    const int t = blockIdx.x * THREADS + threadIdx.x;
    const int n = t >> 1;
    const unsigned s = (unsigned)(t & 1);

    float x0, x1, x2;
    load_point(x, n, x0, x1, x2);

    do_pair<0>(table, out, x0, x1, x2, s, n);
    do_pair<2>(table, out, x0, x1, x2, s, n);
}

template <int L0>
__global__ __launch_bounds__(THREADS)
void hashgrid_pair_kernel(const float* __restrict__ x,
                          const float4* __restrict__ table,
                          float4* __restrict__ out)
{
    const int t = blockIdx.x * THREADS + threadIdx.x;
    const int n = t >> 1;
    const unsigned s = (unsigned)(t & 1);

    float x0, x1, x2;
    load_point(x, n, x0, x1, x2);

    do_pair<L0>(table, out, x0, x1, x2, s, n);
}

extern "C" void kernel_launch(void* const* d_in, const int* in_sizes, int n_in,
                              void* d_out, int out_size)
{
    const float*  x     = (const float*)d_in[0];
    const float4* table = (const float4*)d_in[1];
    float4*       out   = (float4*)d_out;

    hashgrid_quad_kernel   <<<BLOCKS, THREADS>>>(x, table, out);
    hashgrid_pair_kernel<4><<<BLOCKS, THREADS>>>(x, table, out);
    hashgrid_pair_kernel<6><<<BLOCKS, THREADS>>>(x, table, out);
    hashgrid_pair_kernel<8><<<BLOCKS, THREADS>>>(x, table, out);
}